// round 2
// baseline (speedup 1.0000x reference)
#include <cuda_runtime.h>
#include <cstddef>

#define L   2048
#define D   1024
#define H   16
#define KS  1024
#define VS  1024
#define HID 4096
#define HD  64

// ---------------- scratch (device globals; no allocation allowed) ----------
__device__ float g_q[L * KS];                 // 8 MB
__device__ float g_k[L * KS];                 // 8 MB
__device__ float g_v[L * VS];                 // 8 MB
__device__ float g_t0[L * HID];               // 32 MB (stage-1 qkv temp + FFN hidden)
__device__ float g_att[(size_t)H * L * L];    // 256 MB
__device__ float g_sp[L * L];                 // 16 MB
__device__ float g_o[L * VS];                 // 8 MB (attention context)
__device__ float g_h[L * D];                  // 8 MB (post-LN1)
__device__ float g_f[L * D];                  // 8 MB (proj / ffn out)

// ---------------- reductions ----------------------------------------------
__device__ __forceinline__ float warpRedSum(float v) {
#pragma unroll
    for (int o = 16; o > 0; o >>= 1) v += __shfl_xor_sync(0xffffffffu, v, o);
    return v;
}
__device__ __forceinline__ float warpRedMax(float v) {
#pragma unroll
    for (int o = 16; o > 0; o >>= 1) v = fmaxf(v, __shfl_xor_sync(0xffffffffu, v, o));
    return v;
}
// 256-thread block reductions; sred must be float[8]
__device__ __forceinline__ float blockRedSum(float v, float* sred) {
    int lane = threadIdx.x & 31, w = threadIdx.x >> 5;
    v = warpRedSum(v);
    if (lane == 0) sred[w] = v;
    __syncthreads();
    float r;
    if (threadIdx.x < 32) {
        r = (threadIdx.x < 8) ? sred[threadIdx.x] : 0.0f;
        r = warpRedSum(r);
        if (threadIdx.x == 0) sred[0] = r;
    }
    __syncthreads();
    r = sred[0];
    __syncthreads();
    return r;
}
__device__ __forceinline__ float blockRedMax(float v, float* sred) {
    int lane = threadIdx.x & 31, w = threadIdx.x >> 5;
    v = warpRedMax(v);
    if (lane == 0) sred[w] = v;
    __syncthreads();
    float r;
    if (threadIdx.x < 32) {
        r = (threadIdx.x < 8) ? sred[threadIdx.x] : -3.4e38f;
        r = warpRedMax(r);
        if (threadIdx.x == 0) sred[0] = r;
    }
    __syncthreads();
    r = sred[0];
    __syncthreads();
    return r;
}

// ---------------- GEMM: C[M,N] = act(A[M,K] @ W[N,K]^T + bias[N]) ----------
// 64x64 tile, BK=16, 256 threads, 4x4 per thread. M,N %64==0, K %16==0.
template <int RELU>
__global__ void gemm_nt(const float* __restrict__ A, const float* __restrict__ W,
                        const float* __restrict__ bias, float* __restrict__ C,
                        int M, int N, int K) {
    __shared__ float As[16][65];
    __shared__ float Bs[16][65];
    int tid = threadIdx.x;
    int tx = tid & 15, ty = tid >> 4;
    int bm = blockIdx.y * 64, bn = blockIdx.x * 64;
    int lr = tid >> 2;            // 0..63
    int lc4 = (tid & 3) << 2;     // 0,4,8,12

    float acc[4][4] = {};
    const float* Ar = A + (size_t)(bm + lr) * K + lc4;
    const float* Wr = W + (size_t)(bn + lr) * K + lc4;

    for (int k0 = 0; k0 < K; k0 += 16) {
        float4 a = *(const float4*)(Ar + k0);
        As[lc4 + 0][lr] = a.x; As[lc4 + 1][lr] = a.y;
        As[lc4 + 2][lr] = a.z; As[lc4 + 3][lr] = a.w;
        float4 b = *(const float4*)(Wr + k0);
        Bs[lc4 + 0][lr] = b.x; Bs[lc4 + 1][lr] = b.y;
        Bs[lc4 + 2][lr] = b.z; Bs[lc4 + 3][lr] = b.w;
        __syncthreads();
#pragma unroll
        for (int kk = 0; kk < 16; kk++) {
            float ra[4], rb[4];
#pragma unroll
            for (int i = 0; i < 4; i++) ra[i] = As[kk][ty * 4 + i];
#pragma unroll
            for (int j = 0; j < 4; j++) rb[j] = Bs[kk][tx * 4 + j];
#pragma unroll
            for (int i = 0; i < 4; i++)
#pragma unroll
                for (int j = 0; j < 4; j++) acc[i][j] += ra[i] * rb[j];
        }
        __syncthreads();
    }
#pragma unroll
    for (int i = 0; i < 4; i++) {
        int r = bm + ty * 4 + i;
#pragma unroll
        for (int j = 0; j < 4; j++) {
            int c = bn + tx * 4 + j;
            float v = acc[i][j] + bias[c];
            if (RELU) v = fmaxf(v, 0.0f);
            C[(size_t)r * N + c] = v;
        }
    }
}

// ---------------- attention scores: att[h] = q_h k_h^T / 8 + sp_bias ------
// q,k: [L, KS] with head h at cols [h*64, h*64+64). grid (L/64, L/64, H).
__global__ void attn_scores(const float* __restrict__ q, const float* __restrict__ k,
                            const float* __restrict__ sp, float* __restrict__ att) {
    __shared__ float As[16][65];
    __shared__ float Bs[16][65];
    int h = blockIdx.z;
    int tid = threadIdx.x;
    int tx = tid & 15, ty = tid >> 4;
    int bm = blockIdx.y * 64, bn = blockIdx.x * 64;
    int lr = tid >> 2, lc4 = (tid & 3) << 2;

    const float* A = q + h * HD;
    const float* B = k + h * HD;
    float acc[4][4] = {};
    for (int k0 = 0; k0 < HD; k0 += 16) {
        float4 a = *(const float4*)&A[(size_t)(bm + lr) * KS + k0 + lc4];
        As[lc4 + 0][lr] = a.x; As[lc4 + 1][lr] = a.y;
        As[lc4 + 2][lr] = a.z; As[lc4 + 3][lr] = a.w;
        float4 b = *(const float4*)&B[(size_t)(bn + lr) * KS + k0 + lc4];
        Bs[lc4 + 0][lr] = b.x; Bs[lc4 + 1][lr] = b.y;
        Bs[lc4 + 2][lr] = b.z; Bs[lc4 + 3][lr] = b.w;
        __syncthreads();
#pragma unroll
        for (int kk = 0; kk < 16; kk++) {
            float ra[4], rb[4];
#pragma unroll
            for (int i = 0; i < 4; i++) ra[i] = As[kk][ty * 4 + i];
#pragma unroll
            for (int j = 0; j < 4; j++) rb[j] = Bs[kk][tx * 4 + j];
#pragma unroll
            for (int i = 0; i < 4; i++)
#pragma unroll
                for (int j = 0; j < 4; j++) acc[i][j] += ra[i] * rb[j];
        }
        __syncthreads();
    }
    size_t base = (size_t)h * L * L;
#pragma unroll
    for (int i = 0; i < 4; i++) {
        int r = bm + ty * 4 + i;
#pragma unroll
        for (int j = 0; j < 4; j++) {
            int c = bn + tx * 4 + j;
            att[base + (size_t)r * L + c] = acc[i][j] * 0.125f + sp[(size_t)r * L + c];
        }
    }
}

// ---------------- row softmax over 2048 cols; out = scale * softmax(in) ---
__global__ void softmax_row2048(const float* __restrict__ in, float* __restrict__ out,
                                float outscale) {
    __shared__ float sred[8];
    size_t row = blockIdx.x;
    const float* p = in + row * 2048;
    float* o = out + row * 2048;
    int tid = threadIdx.x;   // 256
    float v[8];
    float4 a = *(const float4*)&p[tid * 8];
    float4 b = *(const float4*)&p[tid * 8 + 4];
    v[0] = a.x; v[1] = a.y; v[2] = a.z; v[3] = a.w;
    v[4] = b.x; v[5] = b.y; v[6] = b.z; v[7] = b.w;
    float m = v[0];
#pragma unroll
    for (int i = 1; i < 8; i++) m = fmaxf(m, v[i]);
    m = blockRedMax(m, sred);
    float s = 0.0f;
#pragma unroll
    for (int i = 0; i < 8; i++) { v[i] = __expf(v[i] - m); s += v[i]; }
    s = blockRedSum(s, sred);
    float inv = outscale / s;
    float4 oa, ob;
    oa.x = v[0] * inv; oa.y = v[1] * inv; oa.z = v[2] * inv; oa.w = v[3] * inv;
    ob.x = v[4] * inv; ob.y = v[5] * inv; ob.z = v[6] * inv; ob.w = v[7] * inv;
    *(float4*)&o[tid * 8] = oa;
    *(float4*)&o[tid * 8 + 4] = ob;
}

// ---------------- AV: o[:, h*64:h*64+64] = att[h] @ v_h -------------------
// grid (1, L/64, H)
__global__ void attn_av(const float* __restrict__ att, const float* __restrict__ v,
                        float* __restrict__ o) {
    __shared__ float As[16][65];
    __shared__ float Bs[16][65];
    int h = blockIdx.z;
    int tid = threadIdx.x;
    int tx = tid & 15, ty = tid >> 4;
    int bm = blockIdx.y * 64;
    int lr = tid >> 2, lc4 = (tid & 3) << 2;   // A loader
    int br = tid >> 4, bc4 = (tid & 15) << 2;  // B loader
    const float* A = att + (size_t)h * L * L;
    const float* B = v + h * HD;
    float acc[4][4] = {};
    for (int k0 = 0; k0 < L; k0 += 16) {
        float4 a = *(const float4*)&A[(size_t)(bm + lr) * L + k0 + lc4];
        As[lc4 + 0][lr] = a.x; As[lc4 + 1][lr] = a.y;
        As[lc4 + 2][lr] = a.z; As[lc4 + 3][lr] = a.w;
        float4 b = *(const float4*)&B[(size_t)(k0 + br) * VS + bc4];
        Bs[br][bc4 + 0] = b.x; Bs[br][bc4 + 1] = b.y;
        Bs[br][bc4 + 2] = b.z; Bs[br][bc4 + 3] = b.w;
        __syncthreads();
#pragma unroll
        for (int kk = 0; kk < 16; kk++) {
            float ra[4], rb[4];
#pragma unroll
            for (int i = 0; i < 4; i++) ra[i] = As[kk][ty * 4 + i];
#pragma unroll
            for (int j = 0; j < 4; j++) rb[j] = Bs[kk][tx * 4 + j];
#pragma unroll
            for (int i = 0; i < 4; i++)
#pragma unroll
                for (int j = 0; j < 4; j++) acc[i][j] += ra[i] * rb[j];
        }
        __syncthreads();
    }
#pragma unroll
    for (int i = 0; i < 4; i++) {
        int r = bm + ty * 4 + i;
#pragma unroll
        for (int j = 0; j < 4; j++)
            o[(size_t)r * VS + h * HD + tx * 4 + j] = acc[i][j];
    }
}

// ---------------- fused residual + LayerNorm (row of 1024) ----------------
__global__ void add_ln(const float* __restrict__ a, const float* __restrict__ b,
                       const float* __restrict__ g, const float* __restrict__ be,
                       float* __restrict__ out) {
    __shared__ float sred[8];
    int row = blockIdx.x;
    int tid = threadIdx.x;  // 256, 4 elems each
    size_t base = (size_t)row * 1024 + tid * 4;
    float4 va = *(const float4*)&a[base];
    float4 vb = *(const float4*)&b[base];
    float4 s;
    s.x = va.x + vb.x; s.y = va.y + vb.y; s.z = va.z + vb.z; s.w = va.w + vb.w;
    float sum = s.x + s.y + s.z + s.w;
    float sq = s.x * s.x + s.y * s.y + s.z * s.z + s.w * s.w;
    sum = blockRedSum(sum, sred);
    sq = blockRedSum(sq, sred);
    float mean = sum * (1.0f / 1024.0f);
    float var = sq * (1.0f / 1024.0f) - mean * mean;
    float r = rsqrtf(var + 1e-5f);
    float4 vg = *(const float4*)&g[tid * 4];
    float4 vbe = *(const float4*)&be[tid * 4];
    float4 o;
    o.x = (s.x - mean) * r * vg.x + vbe.x;
    o.y = (s.y - mean) * r * vg.y + vbe.y;
    o.z = (s.z - mean) * r * vg.z + vbe.z;
    o.w = (s.w - mean) * r * vg.w + vbe.w;
    *(float4*)&out[base] = o;
}

// ---------------- launch ---------------------------------------------------
extern "C" void kernel_launch(void* const* d_in, const int* in_sizes, int n_in,
                              void* d_out, int out_size) {
    const float* x   = (const float*)d_in[0];
    const float* sp  = (const float*)d_in[1];
    const float* Wq  = (const float*)d_in[2];
    const float* bq  = (const float*)d_in[3];
    const float* Wk  = (const float*)d_in[4];
    const float* bk  = (const float*)d_in[5];
    const float* Wv  = (const float*)d_in[6];
    const float* bv  = (const float*)d_in[7];
    const float* Wqp = (const float*)d_in[8];
    const float* bqp = (const float*)d_in[9];
    const float* Wkp = (const float*)d_in[10];
    const float* bkp = (const float*)d_in[11];
    const float* Wvp = (const float*)d_in[12];
    const float* bvp = (const float*)d_in[13];
    const float* Wo  = (const float*)d_in[14];
    const float* bo  = (const float*)d_in[15];
    const float* W1  = (const float*)d_in[16];
    const float* b1  = (const float*)d_in[17];
    const float* W2  = (const float*)d_in[18];
    const float* b2  = (const float*)d_in[19];
    const float* g1  = (const float*)d_in[20];
    const float* be1 = (const float*)d_in[21];
    const float* g2  = (const float*)d_in[22];
    const float* be2 = (const float*)d_in[23];
    float* out = (float*)d_out;

    float *pq, *pk, *pv, *pt0, *patt, *psp, *po, *ph, *pf;
    cudaGetSymbolAddress((void**)&pq,  g_q);
    cudaGetSymbolAddress((void**)&pk,  g_k);
    cudaGetSymbolAddress((void**)&pv,  g_v);
    cudaGetSymbolAddress((void**)&pt0, g_t0);
    cudaGetSymbolAddress((void**)&patt, g_att);
    cudaGetSymbolAddress((void**)&psp, g_sp);
    cudaGetSymbolAddress((void**)&po,  g_o);
    cudaGetSymbolAddress((void**)&ph,  g_h);
    cudaGetSymbolAddress((void**)&pf,  g_f);

    dim3 blk(256);

    // Q/K/V double projections
    gemm_nt<0><<<dim3(KS / 64, L / 64), blk>>>(x,   Wq,  bq,  pt0, L, KS, D);
    gemm_nt<0><<<dim3(KS / 64, L / 64), blk>>>(pt0, Wqp, bqp, pq,  L, KS, KS);
    gemm_nt<0><<<dim3(KS / 64, L / 64), blk>>>(x,   Wk,  bk,  pt0, L, KS, D);
    gemm_nt<0><<<dim3(KS / 64, L / 64), blk>>>(pt0, Wkp, bkp, pk,  L, KS, KS);
    gemm_nt<0><<<dim3(VS / 64, L / 64), blk>>>(x,   Wv,  bv,  pt0, L, VS, D);
    gemm_nt<0><<<dim3(VS / 64, L / 64), blk>>>(pt0, Wvp, bvp, pv,  L, VS, VS);

    // sp_bias = 0.5 * softmax(shortest_path, axis=-1)
    softmax_row2048<<<L, blk>>>(sp, psp, 0.5f);

    // att = softmax(qk^T/8 + sp_bias)
    attn_scores<<<dim3(L / 64, L / 64, H), blk>>>(pq, pk, psp, patt);
    softmax_row2048<<<H * L, blk>>>(patt, patt, 1.0f);

    // context = att @ v   ->  [L, VS]
    attn_av<<<dim3(1, L / 64, H), blk>>>(patt, pv, po);

    // o-proj, residual + LN1
    gemm_nt<0><<<dim3(D / 64, L / 64), blk>>>(po, Wo, bo, pf, L, D, VS);
    add_ln<<<L, blk>>>(x, pf, g1, be1, ph);

    // FFN: relu(relu(h W1^T + b1) W2^T + b2), residual + LN2
    gemm_nt<1><<<dim3(HID / 64, L / 64), blk>>>(ph,  W1, b1, pt0, L, HID, D);
    gemm_nt<1><<<dim3(D / 64, L / 64), blk>>>(pt0, W2, b2, pf,  L, D, HID);
    add_ln<<<L, blk>>>(ph, pf, g2, be2, out);
}

// round 4
// speedup vs baseline: 2.4122x; 2.4122x over previous
#include <cuda_runtime.h>
#include <cstddef>
#include <cstdint>

#define L   2048
#define D   1024
#define H   16
#define KS  1024
#define VS  1024
#define HID 4096
#define HD  64

// ---------------- scratch (device globals; no allocation allowed) ----------
__device__ float g_q[L * KS];                 // 8 MB
__device__ float g_k[L * KS];                 // 8 MB
__device__ float g_v[L * VS];                 // 8 MB
__device__ float g_vt[VS * L];                // 8 MB (V transposed per-column)
__device__ float g_t0[L * HID];               // 32 MB
__device__ float g_att[(size_t)H * L * L];    // 256 MB
__device__ float g_sp[L * L];                 // 16 MB
__device__ float g_o[L * VS];                 // 8 MB
__device__ float g_h[L * D];                  // 8 MB
__device__ float g_f[L * D];                  // 8 MB

// ---------------- helpers ---------------------------------------------------
__device__ __forceinline__ unsigned f2tf32(float x) {
    unsigned r;
    asm("cvt.rna.tf32.f32 %0, %1;" : "=r"(r) : "f"(x));
    return r;
}

__device__ __forceinline__ void mma_tf32(float* c, const unsigned* a, const unsigned* b) {
    asm volatile(
        "mma.sync.aligned.m16n8k8.row.col.f32.tf32.tf32.f32 "
        "{%0,%1,%2,%3}, {%4,%5,%6,%7}, {%8,%9}, {%0,%1,%2,%3};\n"
        : "+f"(c[0]), "+f"(c[1]), "+f"(c[2]), "+f"(c[3])
        : "r"(a[0]), "r"(a[1]), "r"(a[2]), "r"(a[3]), "r"(b[0]), "r"(b[1]));
}

__device__ __forceinline__ float warpRedSum(float v) {
#pragma unroll
    for (int o = 16; o > 0; o >>= 1) v += __shfl_xor_sync(0xffffffffu, v, o);
    return v;
}
__device__ __forceinline__ float warpRedMax(float v) {
#pragma unroll
    for (int o = 16; o > 0; o >>= 1) v = fmaxf(v, __shfl_xor_sync(0xffffffffu, v, o));
    return v;
}
__device__ __forceinline__ float blockRedSum(float v, float* sred) {
    int lane = threadIdx.x & 31, w = threadIdx.x >> 5;
    v = warpRedSum(v);
    if (lane == 0) sred[w] = v;
    __syncthreads();
    float r;
    if (threadIdx.x < 32) {
        r = (threadIdx.x < 8) ? sred[threadIdx.x] : 0.0f;
        r = warpRedSum(r);
        if (threadIdx.x == 0) sred[0] = r;
    }
    __syncthreads();
    r = sred[0];
    __syncthreads();
    return r;
}
__device__ __forceinline__ float blockRedMax(float v, float* sred) {
    int lane = threadIdx.x & 31, w = threadIdx.x >> 5;
    v = warpRedMax(v);
    if (lane == 0) sred[w] = v;
    __syncthreads();
    float r;
    if (threadIdx.x < 32) {
        r = (threadIdx.x < 8) ? sred[threadIdx.x] : -3.4e38f;
        r = warpRedMax(r);
        if (threadIdx.x == 0) sred[0] = r;
    }
    __syncthreads();
    r = sred[0];
    __syncthreads();
    return r;
}

// ---------------- TF32 tensor-core NT GEMM ---------------------------------
// C[M,N] = act(A[M,K] @ W[N,K]^T + bias). 128x128 tile, BK=16, 256 threads.
// Warps 2(m) x 4(n); warp tile 64x32: 4 m16-tiles x 4 n8-tiles.
template <int RELU>
__global__ void gemm_tc(const float* __restrict__ A, const float* __restrict__ W,
                        const float* __restrict__ bias, float* __restrict__ C,
                        int M, int N, int K) {
    __shared__ unsigned As[128][20];
    __shared__ unsigned Ws[128][20];
    int tid = threadIdx.x;
    int wid = tid >> 5, lane = tid & 31;
    int g = lane >> 2, c = lane & 3;
    int wm = wid >> 2, wn = wid & 3;
    int bm = blockIdx.y * 128, bn = blockIdx.x * 128;

    float acc[4][4][4] = {};

    int lr = tid >> 1, lkc = (tid & 1) * 8;
    const float* Ap = A + (size_t)(bm + lr) * K + lkc;
    const float* Wp = W + (size_t)(bn + lr) * K + lkc;

    for (int k0 = 0; k0 < K; k0 += 16) {
        float4 a0 = *(const float4*)(Ap + k0);
        float4 a1 = *(const float4*)(Ap + k0 + 4);
        float4 w0 = *(const float4*)(Wp + k0);
        float4 w1 = *(const float4*)(Wp + k0 + 4);
        uint4 ua0 = {f2tf32(a0.x), f2tf32(a0.y), f2tf32(a0.z), f2tf32(a0.w)};
        uint4 ua1 = {f2tf32(a1.x), f2tf32(a1.y), f2tf32(a1.z), f2tf32(a1.w)};
        uint4 uw0 = {f2tf32(w0.x), f2tf32(w0.y), f2tf32(w0.z), f2tf32(w0.w)};
        uint4 uw1 = {f2tf32(w1.x), f2tf32(w1.y), f2tf32(w1.z), f2tf32(w1.w)};
        *(uint4*)&As[lr][lkc]     = ua0;
        *(uint4*)&As[lr][lkc + 4] = ua1;
        *(uint4*)&Ws[lr][lkc]     = uw0;
        *(uint4*)&Ws[lr][lkc + 4] = uw1;
        __syncthreads();
#pragma unroll
        for (int ks = 0; ks < 2; ks++) {
            int kk = ks * 8;
            unsigned af[4][4], bf[4][2];
#pragma unroll
            for (int mt = 0; mt < 4; mt++) {
                int rm = wm * 64 + mt * 16 + g;
                af[mt][0] = As[rm][kk + c];
                af[mt][1] = As[rm + 8][kk + c];
                af[mt][2] = As[rm][kk + c + 4];
                af[mt][3] = As[rm + 8][kk + c + 4];
            }
#pragma unroll
            for (int nt = 0; nt < 4; nt++) {
                int rn = wn * 32 + nt * 8 + g;
                bf[nt][0] = Ws[rn][kk + c];
                bf[nt][1] = Ws[rn][kk + c + 4];
            }
#pragma unroll
            for (int mt = 0; mt < 4; mt++)
#pragma unroll
                for (int nt = 0; nt < 4; nt++)
                    mma_tf32(acc[mt][nt], af[mt], bf[nt]);
        }
        __syncthreads();
    }
#pragma unroll
    for (int mt = 0; mt < 4; mt++) {
        int row = bm + wm * 64 + mt * 16 + g;
#pragma unroll
        for (int nt = 0; nt < 4; nt++) {
            int col = bn + wn * 32 + nt * 8 + 2 * c;
            float2 bv = *(const float2*)&bias[col];
            float v0 = acc[mt][nt][0] + bv.x;
            float v1 = acc[mt][nt][1] + bv.y;
            float v2 = acc[mt][nt][2] + bv.x;
            float v3 = acc[mt][nt][3] + bv.y;
            if (RELU) {
                v0 = fmaxf(v0, 0.0f); v1 = fmaxf(v1, 0.0f);
                v2 = fmaxf(v2, 0.0f); v3 = fmaxf(v3, 0.0f);
            }
            *(float2*)&C[(size_t)row * N + col] = make_float2(v0, v1);
            *(float2*)&C[(size_t)(row + 8) * N + col] = make_float2(v2, v3);
        }
    }
}

// ---------------- attention scores (TF32 MMA) -------------------------------
// att[h] = q_h @ k_h^T * 0.125 + sp. q,k: [L,KS], head cols [h*64, h*64+64).
__global__ void attn_scores_tc(const float* __restrict__ q, const float* __restrict__ k,
                               const float* __restrict__ sp, float* __restrict__ att) {
    __shared__ unsigned As[128][20];
    __shared__ unsigned Ws[128][20];
    int h = blockIdx.z;
    int tid = threadIdx.x;
    int wid = tid >> 5, lane = tid & 31;
    int g = lane >> 2, c = lane & 3;
    int wm = wid >> 2, wn = wid & 3;
    int bm = blockIdx.y * 128, bn = blockIdx.x * 128;

    float acc[4][4][4] = {};

    int lr = tid >> 1, lkc = (tid & 1) * 8;
    const float* Ap = q + h * HD + (size_t)(bm + lr) * KS + lkc;
    const float* Wp = k + h * HD + (size_t)(bn + lr) * KS + lkc;

    for (int k0 = 0; k0 < HD; k0 += 16) {
        float4 a0 = *(const float4*)(Ap + k0);
        float4 a1 = *(const float4*)(Ap + k0 + 4);
        float4 w0 = *(const float4*)(Wp + k0);
        float4 w1 = *(const float4*)(Wp + k0 + 4);
        uint4 ua0 = {f2tf32(a0.x), f2tf32(a0.y), f2tf32(a0.z), f2tf32(a0.w)};
        uint4 ua1 = {f2tf32(a1.x), f2tf32(a1.y), f2tf32(a1.z), f2tf32(a1.w)};
        uint4 uw0 = {f2tf32(w0.x), f2tf32(w0.y), f2tf32(w0.z), f2tf32(w0.w)};
        uint4 uw1 = {f2tf32(w1.x), f2tf32(w1.y), f2tf32(w1.z), f2tf32(w1.w)};
        *(uint4*)&As[lr][lkc]     = ua0;
        *(uint4*)&As[lr][lkc + 4] = ua1;
        *(uint4*)&Ws[lr][lkc]     = uw0;
        *(uint4*)&Ws[lr][lkc + 4] = uw1;
        __syncthreads();
#pragma unroll
        for (int ks = 0; ks < 2; ks++) {
            int kk = ks * 8;
            unsigned af[4][4], bf[4][2];
#pragma unroll
            for (int mt = 0; mt < 4; mt++) {
                int rm = wm * 64 + mt * 16 + g;
                af[mt][0] = As[rm][kk + c];
                af[mt][1] = As[rm + 8][kk + c];
                af[mt][2] = As[rm][kk + c + 4];
                af[mt][3] = As[rm + 8][kk + c + 4];
            }
#pragma unroll
            for (int nt = 0; nt < 4; nt++) {
                int rn = wn * 32 + nt * 8 + g;
                bf[nt][0] = Ws[rn][kk + c];
                bf[nt][1] = Ws[rn][kk + c + 4];
            }
#pragma unroll
            for (int mt = 0; mt < 4; mt++)
#pragma unroll
                for (int nt = 0; nt < 4; nt++)
                    mma_tf32(acc[mt][nt], af[mt], bf[nt]);
        }
        __syncthreads();
    }
    size_t base = (size_t)h * L * L;
#pragma unroll
    for (int mt = 0; mt < 4; mt++) {
        int row = bm + wm * 64 + mt * 16 + g;
#pragma unroll
        for (int nt = 0; nt < 4; nt++) {
            int col = bn + wn * 32 + nt * 8 + 2 * c;
            float2 s0 = *(const float2*)&sp[(size_t)row * L + col];
            float2 s1 = *(const float2*)&sp[(size_t)(row + 8) * L + col];
            *(float2*)&att[base + (size_t)row * L + col] =
                make_float2(acc[mt][nt][0] * 0.125f + s0.x, acc[mt][nt][1] * 0.125f + s0.y);
            *(float2*)&att[base + (size_t)(row + 8) * L + col] =
                make_float2(acc[mt][nt][2] * 0.125f + s1.x, acc[mt][nt][3] * 0.125f + s1.y);
        }
    }
}

// ---------------- AV (TF32 MMA): o[:, h*64:+64] = att[h] @ vt_h^T -----------
// vt: [VS, L] where vt[c][r] = v[r][c]; head h rows [h*64, h*64+64).
// 128x64 tile. Warps 4(m) x 2(n); warp tile 32x32: 2 m-tiles x 4 n-tiles.
__global__ void attn_av_tc(const float* __restrict__ att, const float* __restrict__ vt,
                           float* __restrict__ o) {
    __shared__ unsigned As[128][20];
    __shared__ unsigned Ws[64][20];
    int h = blockIdx.z;
    int tid = threadIdx.x;
    int wid = tid >> 5, lane = tid & 31;
    int g = lane >> 2, c = lane & 3;
    int wm = wid >> 1, wn = wid & 1;
    int bm = blockIdx.y * 128;

    float acc[2][4][4] = {};

    int lr = tid >> 1, lkc = (tid & 1) * 8;
    const float* Ap = att + (size_t)h * L * L + (size_t)(bm + lr) * L + lkc;
    int wr = tid >> 2, wkc = (tid & 3) * 4;
    const float* Wp = vt + (size_t)(h * HD + wr) * L + wkc;

    for (int k0 = 0; k0 < L; k0 += 16) {
        float4 a0 = *(const float4*)(Ap + k0);
        float4 a1 = *(const float4*)(Ap + k0 + 4);
        float4 w0 = *(const float4*)(Wp + k0);
        uint4 ua0 = {f2tf32(a0.x), f2tf32(a0.y), f2tf32(a0.z), f2tf32(a0.w)};
        uint4 ua1 = {f2tf32(a1.x), f2tf32(a1.y), f2tf32(a1.z), f2tf32(a1.w)};
        uint4 uw0 = {f2tf32(w0.x), f2tf32(w0.y), f2tf32(w0.z), f2tf32(w0.w)};
        *(uint4*)&As[lr][lkc]     = ua0;
        *(uint4*)&As[lr][lkc + 4] = ua1;
        *(uint4*)&Ws[wr][wkc]     = uw0;
        __syncthreads();
#pragma unroll
        for (int ks = 0; ks < 2; ks++) {
            int kk = ks * 8;
            unsigned af[2][4], bf[4][2];
#pragma unroll
            for (int mt = 0; mt < 2; mt++) {
                int rm = wm * 32 + mt * 16 + g;
                af[mt][0] = As[rm][kk + c];
                af[mt][1] = As[rm + 8][kk + c];
                af[mt][2] = As[rm][kk + c + 4];
                af[mt][3] = As[rm + 8][kk + c + 4];
            }
#pragma unroll
            for (int nt = 0; nt < 4; nt++) {
                int rn = wn * 32 + nt * 8 + g;
                bf[nt][0] = Ws[rn][kk + c];
                bf[nt][1] = Ws[rn][kk + c + 4];
            }
#pragma unroll
            for (int mt = 0; mt < 2; mt++)
#pragma unroll
                for (int nt = 0; nt < 4; nt++)
                    mma_tf32(acc[mt][nt], af[mt], bf[nt]);
        }
        __syncthreads();
    }
#pragma unroll
    for (int mt = 0; mt < 2; mt++) {
        int row = bm + wm * 32 + mt * 16 + g;
#pragma unroll
        for (int nt = 0; nt < 4; nt++) {
            int col = h * HD + wn * 32 + nt * 8 + 2 * c;
            *(float2*)&o[(size_t)row * VS + col] =
                make_float2(acc[mt][nt][0], acc[mt][nt][1]);
            *(float2*)&o[(size_t)(row + 8) * VS + col] =
                make_float2(acc[mt][nt][2], acc[mt][nt][3]);
        }
    }
}

// ---------------- transpose: out[c][r] = in[r][c]; in [R x Cc] --------------
__global__ void transpose_k(const float* __restrict__ in, float* __restrict__ out,
                            int R, int Cc) {
    __shared__ float t[32][33];
    int c0 = blockIdx.x * 32, r0 = blockIdx.y * 32;
    int tx = threadIdx.x, ty = threadIdx.y;  // 32 x 8
#pragma unroll
    for (int i = 0; i < 4; i++)
        t[ty + i * 8][tx] = in[(size_t)(r0 + ty + i * 8) * Cc + c0 + tx];
    __syncthreads();
#pragma unroll
    for (int i = 0; i < 4; i++)
        out[(size_t)(c0 + ty + i * 8) * R + r0 + tx] = t[tx][ty + i * 8];
}

// ---------------- row softmax over 2048 cols --------------------------------
__global__ void softmax_row2048(const float* __restrict__ in, float* __restrict__ out,
                                float outscale) {
    __shared__ float sred[8];
    size_t row = blockIdx.x;
    const float* p = in + row * 2048;
    float* o = out + row * 2048;
    int tid = threadIdx.x;
    float v[8];
    float4 a = *(const float4*)&p[tid * 8];
    float4 b = *(const float4*)&p[tid * 8 + 4];
    v[0] = a.x; v[1] = a.y; v[2] = a.z; v[3] = a.w;
    v[4] = b.x; v[5] = b.y; v[6] = b.z; v[7] = b.w;
    float m = v[0];
#pragma unroll
    for (int i = 1; i < 8; i++) m = fmaxf(m, v[i]);
    m = blockRedMax(m, sred);
    float s = 0.0f;
#pragma unroll
    for (int i = 0; i < 8; i++) { v[i] = __expf(v[i] - m); s += v[i]; }
    s = blockRedSum(s, sred);
    float inv = outscale / s;
    float4 oa, ob;
    oa.x = v[0] * inv; oa.y = v[1] * inv; oa.z = v[2] * inv; oa.w = v[3] * inv;
    ob.x = v[4] * inv; ob.y = v[5] * inv; ob.z = v[6] * inv; ob.w = v[7] * inv;
    *(float4*)&o[tid * 8] = oa;
    *(float4*)&o[tid * 8 + 4] = ob;
}

// ---------------- fused residual + LayerNorm --------------------------------
__global__ void add_ln(const float* __restrict__ a, const float* __restrict__ b,
                       const float* __restrict__ g, const float* __restrict__ be,
                       float* __restrict__ out) {
    __shared__ float sred[8];
    int row = blockIdx.x;
    int tid = threadIdx.x;
    size_t base = (size_t)row * 1024 + tid * 4;
    float4 va = *(const float4*)&a[base];
    float4 vb = *(const float4*)&b[base];
    float4 s;
    s.x = va.x + vb.x; s.y = va.y + vb.y; s.z = va.z + vb.z; s.w = va.w + vb.w;
    float sum = s.x + s.y + s.z + s.w;
    float sq = s.x * s.x + s.y * s.y + s.z * s.z + s.w * s.w;
    sum = blockRedSum(sum, sred);
    sq = blockRedSum(sq, sred);
    float mean = sum * (1.0f / 1024.0f);
    float var = sq * (1.0f / 1024.0f) - mean * mean;
    float r = rsqrtf(var + 1e-5f);
    float4 vg = *(const float4*)&g[tid * 4];
    float4 vbe = *(const float4*)&be[tid * 4];
    float4 o;
    o.x = (s.x - mean) * r * vg.x + vbe.x;
    o.y = (s.y - mean) * r * vg.y + vbe.y;
    o.z = (s.z - mean) * r * vg.z + vbe.z;
    o.w = (s.w - mean) * r * vg.w + vbe.w;
    *(float4*)&out[base] = o;
}

// ---------------- launch ----------------------------------------------------
extern "C" void kernel_launch(void* const* d_in, const int* in_sizes, int n_in,
                              void* d_out, int out_size) {
    const float* x   = (const float*)d_in[0];
    const float* sp  = (const float*)d_in[1];
    const float* Wq  = (const float*)d_in[2];
    const float* bq  = (const float*)d_in[3];
    const float* Wk  = (const float*)d_in[4];
    const float* bk  = (const float*)d_in[5];
    const float* Wv  = (const float*)d_in[6];
    const float* bv  = (const float*)d_in[7];
    const float* Wqp = (const float*)d_in[8];
    const float* bqp = (const float*)d_in[9];
    const float* Wkp = (const float*)d_in[10];
    const float* bkp = (const float*)d_in[11];
    const float* Wvp = (const float*)d_in[12];
    const float* bvp = (const float*)d_in[13];
    const float* Wo  = (const float*)d_in[14];
    const float* bo  = (const float*)d_in[15];
    const float* W1  = (const float*)d_in[16];
    const float* b1  = (const float*)d_in[17];
    const float* W2  = (const float*)d_in[18];
    const float* b2  = (const float*)d_in[19];
    const float* g1  = (const float*)d_in[20];
    const float* be1 = (const float*)d_in[21];
    const float* g2  = (const float*)d_in[22];
    const float* be2 = (const float*)d_in[23];
    float* out = (float*)d_out;

    float *pq, *pk, *pv, *pvt, *pt0, *patt, *psp, *po, *ph, *pf;
    cudaGetSymbolAddress((void**)&pq,  g_q);
    cudaGetSymbolAddress((void**)&pk,  g_k);
    cudaGetSymbolAddress((void**)&pv,  g_v);
    cudaGetSymbolAddress((void**)&pvt, g_vt);
    cudaGetSymbolAddress((void**)&pt0, g_t0);
    cudaGetSymbolAddress((void**)&patt, g_att);
    cudaGetSymbolAddress((void**)&psp, g_sp);
    cudaGetSymbolAddress((void**)&po,  g_o);
    cudaGetSymbolAddress((void**)&ph,  g_h);
    cudaGetSymbolAddress((void**)&pf,  g_f);

    dim3 blk(256);

    // Q/K/V double projections (tensor cores)
    gemm_tc<0><<<dim3(KS / 128, L / 128), blk>>>(x,   Wq,  bq,  pt0, L, KS, D);
    gemm_tc<0><<<dim3(KS / 128, L / 128), blk>>>(pt0, Wqp, bqp, pq,  L, KS, KS);
    gemm_tc<0><<<dim3(KS / 128, L / 128), blk>>>(x,   Wk,  bk,  pt0, L, KS, D);
    gemm_tc<0><<<dim3(KS / 128, L / 128), blk>>>(pt0, Wkp, bkp, pk,  L, KS, KS);
    gemm_tc<0><<<dim3(VS / 128, L / 128), blk>>>(x,   Wv,  bv,  pt0, L, VS, D);
    gemm_tc<0><<<dim3(VS / 128, L / 128), blk>>>(pt0, Wvp, bvp, pv,  L, VS, VS);

    // v transpose for AV mma
    transpose_k<<<dim3(VS / 32, L / 32), dim3(32, 8)>>>(pv, pvt, L, VS);

    // sp_bias = 0.5 * softmax(shortest_path, axis=-1)
    softmax_row2048<<<L, blk>>>(sp, psp, 0.5f);

    // att = softmax(qk^T/8 + sp_bias)
    attn_scores_tc<<<dim3(L / 128, L / 128, H), blk>>>(pq, pk, psp, patt);
    softmax_row2048<<<H * L, blk>>>(patt, patt, 1.0f);

    // context = att @ v
    attn_av_tc<<<dim3(1, L / 128, H), blk>>>(patt, pvt, po);

    // o-proj, residual + LN1
    gemm_tc<0><<<dim3(D / 128, L / 128), blk>>>(po, Wo, bo, pf, L, D, VS);
    add_ln<<<L, blk>>>(x, pf, g1, be1, ph);

    // FFN, residual + LN2
    gemm_tc<1><<<dim3(HID / 128, L / 128), blk>>>(ph,  W1, b1, pt0, L, HID, D);
    gemm_tc<1><<<dim3(D / 128, L / 128), blk>>>(pt0, W2, b2, pf,  L, D, HID);
    add_ln<<<L, blk>>>(ph, pf, g2, be2, out);
}

// round 6
// speedup vs baseline: 2.9640x; 1.2288x over previous
#include <cuda_runtime.h>
#include <cstddef>
#include <cstdint>

#define L   2048
#define D   1024
#define H   16
#define KS  1024
#define VS  1024
#define HID 4096
#define HD  64

// ---------------- scratch (device globals; no allocation allowed) ----------
__device__ float g_q[L * KS];                 // 8 MB
__device__ float g_k[L * KS];                 // 8 MB
__device__ float g_v[L * VS];                 // 8 MB
__device__ float g_vt[VS * L];                // 8 MB (V transposed per-column)
__device__ float g_t0[L * HID];               // 32 MB
__device__ float g_att[(size_t)H * L * L];    // 256 MB
__device__ float g_sp[L * L];                 // 16 MB
__device__ float g_o[L * VS];                 // 8 MB
__device__ float g_h[L * D];                  // 8 MB
__device__ float g_f[L * D];                  // 8 MB

// ---------------- helpers ---------------------------------------------------
__device__ __forceinline__ unsigned f2tf32(float x) {
    unsigned r;
    asm("cvt.rna.tf32.f32 %0, %1;" : "=r"(r) : "f"(x));
    return r;
}

__device__ __forceinline__ void mma_tf32(float* c, const unsigned* a, const unsigned* b) {
    asm volatile(
        "mma.sync.aligned.m16n8k8.row.col.f32.tf32.tf32.f32 "
        "{%0,%1,%2,%3}, {%4,%5,%6,%7}, {%8,%9}, {%0,%1,%2,%3};\n"
        : "+f"(c[0]), "+f"(c[1]), "+f"(c[2]), "+f"(c[3])
        : "r"(a[0]), "r"(a[1]), "r"(a[2]), "r"(a[3]), "r"(b[0]), "r"(b[1]));
}

__device__ __forceinline__ void cp16(unsigned dst, const void* src) {
    asm volatile("cp.async.ca.shared.global [%0], [%1], 16;\n" :: "r"(dst), "l"(src));
}
#define CP_COMMIT() asm volatile("cp.async.commit_group;\n" ::: "memory")
#define CP_WAIT1()  asm volatile("cp.async.wait_group 1;\n" ::: "memory")
#define CP_WAIT0()  asm volatile("cp.async.wait_group 0;\n" ::: "memory")

__device__ __forceinline__ float warpRedSum(float v) {
#pragma unroll
    for (int o = 16; o > 0; o >>= 1) v += __shfl_xor_sync(0xffffffffu, v, o);
    return v;
}
__device__ __forceinline__ float warpRedMax(float v) {
#pragma unroll
    for (int o = 16; o > 0; o >>= 1) v = fmaxf(v, __shfl_xor_sync(0xffffffffu, v, o));
    return v;
}
__device__ __forceinline__ float blockRedSum(float v, float* sred) {
    int lane = threadIdx.x & 31, w = threadIdx.x >> 5;
    v = warpRedSum(v);
    if (lane == 0) sred[w] = v;
    __syncthreads();
    float r;
    if (threadIdx.x < 32) {
        r = (threadIdx.x < 8) ? sred[threadIdx.x] : 0.0f;
        r = warpRedSum(r);
        if (threadIdx.x == 0) sred[0] = r;
    }
    __syncthreads();
    r = sred[0];
    __syncthreads();
    return r;
}
__device__ __forceinline__ float blockRedMax(float v, float* sred) {
    int lane = threadIdx.x & 31, w = threadIdx.x >> 5;
    v = warpRedMax(v);
    if (lane == 0) sred[w] = v;
    __syncthreads();
    float r;
    if (threadIdx.x < 32) {
        r = (threadIdx.x < 8) ? sred[threadIdx.x] : -3.4e38f;
        r = warpRedMax(r);
        if (threadIdx.x == 0) sred[0] = r;
    }
    __syncthreads();
    r = sred[0];
    __syncthreads();
    return r;
}

// ---------------- TF32 tensor-core NT GEMM, cp.async double-buffered --------
// C[M,N] = act(A[M,K] @ W[N,K]^T + bias). 128x128 tile, BK=16, 256 threads.
// Warps 2(m) x 4(n); warp tile 64x32. fp32 in smem, tf32 cvt at fragment load.
// Smem [128][20]: bank(row,k) = (20*row + k) % 32 -> conflict-free fragments;
// 80-byte row stride keeps 16B cp.async chunks aligned.
template <int RELU>
__global__ void __launch_bounds__(256, 2)
gemm_tc(const float* __restrict__ A, const float* __restrict__ W,
        const float* __restrict__ bias, float* __restrict__ C,
        int M, int N, int K) {
    __shared__ float As[2][128][20];
    __shared__ float Ws[2][128][20];
    int tid = threadIdx.x;
    int wid = tid >> 5, lane = tid & 31;
    int g = lane >> 2, c = lane & 3;
    int wm = wid >> 2, wn = wid & 3;
    int bm = blockIdx.y * 128, bn = blockIdx.x * 128;

    float acc[4][4][4] = {};

    int lrow = tid >> 1;           // 0..127
    int lcol = (tid & 1) * 8;      // 0 or 8
    const float* Ap = A + (size_t)(bm + lrow) * K + lcol;
    const float* Wp = W + (size_t)(bn + lrow) * K + lcol;

    unsigned da0 = (unsigned)__cvta_generic_to_shared(&As[0][lrow][lcol]);
    unsigned dw0 = (unsigned)__cvta_generic_to_shared(&Ws[0][lrow][lcol]);
    const unsigned stage_off = 128 * 20 * 4;

    // prologue: stage 0
    cp16(da0, Ap);      cp16(da0 + 16, Ap + 4);
    cp16(dw0, Wp);      cp16(dw0 + 16, Wp + 4);
    CP_COMMIT();

    for (int k0 = 0; k0 < K; k0 += 16) {
        int s = (k0 >> 4) & 1;
        if (k0 + 16 < K) {
            unsigned da = da0 + (s ^ 1) * stage_off;
            unsigned dw = dw0 + (s ^ 1) * stage_off;
            const float* an = Ap + k0 + 16;
            const float* wn2 = Wp + k0 + 16;
            cp16(da, an);      cp16(da + 16, an + 4);
            cp16(dw, wn2);     cp16(dw + 16, wn2 + 4);
            CP_COMMIT();
            CP_WAIT1();
        } else {
            CP_WAIT0();
        }
        __syncthreads();
#pragma unroll
        for (int ks = 0; ks < 2; ks++) {
            int kk = ks * 8;
            unsigned af[4][4], bf[4][2];
#pragma unroll
            for (int mt = 0; mt < 4; mt++) {
                int rm = wm * 64 + mt * 16 + g;
                af[mt][0] = f2tf32(As[s][rm][kk + c]);
                af[mt][1] = f2tf32(As[s][rm + 8][kk + c]);
                af[mt][2] = f2tf32(As[s][rm][kk + c + 4]);
                af[mt][3] = f2tf32(As[s][rm + 8][kk + c + 4]);
            }
#pragma unroll
            for (int nt = 0; nt < 4; nt++) {
                int rn = wn * 32 + nt * 8 + g;
                bf[nt][0] = f2tf32(Ws[s][rn][kk + c]);
                bf[nt][1] = f2tf32(Ws[s][rn][kk + c + 4]);
            }
#pragma unroll
            for (int mt = 0; mt < 4; mt++)
#pragma unroll
                for (int nt = 0; nt < 4; nt++)
                    mma_tf32(acc[mt][nt], af[mt], bf[nt]);
        }
        __syncthreads();
    }
#pragma unroll
    for (int mt = 0; mt < 4; mt++) {
        int row = bm + wm * 64 + mt * 16 + g;
#pragma unroll
        for (int nt = 0; nt < 4; nt++) {
            int col = bn + wn * 32 + nt * 8 + 2 * c;
            float2 bv = *(const float2*)&bias[col];
            float v0 = acc[mt][nt][0] + bv.x;
            float v1 = acc[mt][nt][1] + bv.y;
            float v2 = acc[mt][nt][2] + bv.x;
            float v3 = acc[mt][nt][3] + bv.y;
            if (RELU) {
                v0 = fmaxf(v0, 0.0f); v1 = fmaxf(v1, 0.0f);
                v2 = fmaxf(v2, 0.0f); v3 = fmaxf(v3, 0.0f);
            }
            *(float2*)&C[(size_t)row * N + col] = make_float2(v0, v1);
            *(float2*)&C[(size_t)(row + 8) * N + col] = make_float2(v2, v3);
        }
    }
}

// ---------------- attention scores (TF32 MMA) -------------------------------
// att[h] = q_h @ k_h^T * 0.125 + sp. q,k: [L,KS], head cols [h*64, h*64+64).
__global__ void attn_scores_tc(const float* __restrict__ q, const float* __restrict__ k,
                               const float* __restrict__ sp, float* __restrict__ att) {
    __shared__ unsigned As[128][20];
    __shared__ unsigned Ws[128][20];
    int h = blockIdx.z;
    int tid = threadIdx.x;
    int wid = tid >> 5, lane = tid & 31;
    int g = lane >> 2, c = lane & 3;
    int wm = wid >> 2, wn = wid & 3;
    int bm = blockIdx.y * 128, bn = blockIdx.x * 128;

    float acc[4][4][4] = {};

    int lr = tid >> 1, lkc = (tid & 1) * 8;
    const float* Ap = q + h * HD + (size_t)(bm + lr) * KS + lkc;
    const float* Wp = k + h * HD + (size_t)(bn + lr) * KS + lkc;

    for (int k0 = 0; k0 < HD; k0 += 16) {
        float4 a0 = *(const float4*)(Ap + k0);
        float4 a1 = *(const float4*)(Ap + k0 + 4);
        float4 w0 = *(const float4*)(Wp + k0);
        float4 w1 = *(const float4*)(Wp + k0 + 4);
        uint4 ua0 = {f2tf32(a0.x), f2tf32(a0.y), f2tf32(a0.z), f2tf32(a0.w)};
        uint4 ua1 = {f2tf32(a1.x), f2tf32(a1.y), f2tf32(a1.z), f2tf32(a1.w)};
        uint4 uw0 = {f2tf32(w0.x), f2tf32(w0.y), f2tf32(w0.z), f2tf32(w0.w)};
        uint4 uw1 = {f2tf32(w1.x), f2tf32(w1.y), f2tf32(w1.z), f2tf32(w1.w)};
        *(uint4*)&As[lr][lkc]     = ua0;
        *(uint4*)&As[lr][lkc + 4] = ua1;
        *(uint4*)&Ws[lr][lkc]     = uw0;
        *(uint4*)&Ws[lr][lkc + 4] = uw1;
        __syncthreads();
#pragma unroll
        for (int ks = 0; ks < 2; ks++) {
            int kk = ks * 8;
            unsigned af[4][4], bf[4][2];
#pragma unroll
            for (int mt = 0; mt < 4; mt++) {
                int rm = wm * 64 + mt * 16 + g;
                af[mt][0] = As[rm][kk + c];
                af[mt][1] = As[rm + 8][kk + c];
                af[mt][2] = As[rm][kk + c + 4];
                af[mt][3] = As[rm + 8][kk + c + 4];
            }
#pragma unroll
            for (int nt = 0; nt < 4; nt++) {
                int rn = wn * 32 + nt * 8 + g;
                bf[nt][0] = Ws[rn][kk + c];
                bf[nt][1] = Ws[rn][kk + c + 4];
            }
#pragma unroll
            for (int mt = 0; mt < 4; mt++)
#pragma unroll
                for (int nt = 0; nt < 4; nt++)
                    mma_tf32(acc[mt][nt], af[mt], bf[nt]);
        }
        __syncthreads();
    }
    size_t base = (size_t)h * L * L;
#pragma unroll
    for (int mt = 0; mt < 4; mt++) {
        int row = bm + wm * 64 + mt * 16 + g;
#pragma unroll
        for (int nt = 0; nt < 4; nt++) {
            int col = bn + wn * 32 + nt * 8 + 2 * c;
            float2 s0 = *(const float2*)&sp[(size_t)row * L + col];
            float2 s1 = *(const float2*)&sp[(size_t)(row + 8) * L + col];
            *(float2*)&att[base + (size_t)row * L + col] =
                make_float2(acc[mt][nt][0] * 0.125f + s0.x, acc[mt][nt][1] * 0.125f + s0.y);
            *(float2*)&att[base + (size_t)(row + 8) * L + col] =
                make_float2(acc[mt][nt][2] * 0.125f + s1.x, acc[mt][nt][3] * 0.125f + s1.y);
        }
    }
}

// ---------------- AV (TF32 MMA): o[:, h*64:+64] = att[h] @ vt_h^T -----------
// vt: [VS, L] where vt[c][r] = v[r][c]; head h rows [h*64, h*64+64).
// 128x64 tile. Warps 4(m) x 2(n); warp tile 32x32: 2 m-tiles x 4 n-tiles.
__global__ void attn_av_tc(const float* __restrict__ att, const float* __restrict__ vt,
                           float* __restrict__ o) {
    __shared__ unsigned As[128][20];
    __shared__ unsigned Ws[64][20];
    int h = blockIdx.z;
    int tid = threadIdx.x;
    int wid = tid >> 5, lane = tid & 31;
    int g = lane >> 2, c = lane & 3;
    int wm = wid >> 1, wn = wid & 1;
    int bm = blockIdx.y * 128;

    float acc[2][4][4] = {};

    int lr = tid >> 1, lkc = (tid & 1) * 8;
    const float* Ap = att + (size_t)h * L * L + (size_t)(bm + lr) * L + lkc;
    int wr = tid >> 2, wkc = (tid & 3) * 4;
    const float* Wp = vt + (size_t)(h * HD + wr) * L + wkc;

    for (int k0 = 0; k0 < L; k0 += 16) {
        float4 a0 = *(const float4*)(Ap + k0);
        float4 a1 = *(const float4*)(Ap + k0 + 4);
        float4 w0 = *(const float4*)(Wp + k0);
        uint4 ua0 = {f2tf32(a0.x), f2tf32(a0.y), f2tf32(a0.z), f2tf32(a0.w)};
        uint4 ua1 = {f2tf32(a1.x), f2tf32(a1.y), f2tf32(a1.z), f2tf32(a1.w)};
        uint4 uw0 = {f2tf32(w0.x), f2tf32(w0.y), f2tf32(w0.z), f2tf32(w0.w)};
        *(uint4*)&As[lr][lkc]     = ua0;
        *(uint4*)&As[lr][lkc + 4] = ua1;
        *(uint4*)&Ws[wr][wkc]     = uw0;
        __syncthreads();
#pragma unroll
        for (int ks = 0; ks < 2; ks++) {
            int kk = ks * 8;
            unsigned af[2][4], bf[4][2];
#pragma unroll
            for (int mt = 0; mt < 2; mt++) {
                int rm = wm * 32 + mt * 16 + g;
                af[mt][0] = As[rm][kk + c];
                af[mt][1] = As[rm + 8][kk + c];
                af[mt][2] = As[rm][kk + c + 4];
                af[mt][3] = As[rm + 8][kk + c + 4];
            }
#pragma unroll
            for (int nt = 0; nt < 4; nt++) {
                int rn = wn * 32 + nt * 8 + g;
                bf[nt][0] = Ws[rn][kk + c];
                bf[nt][1] = Ws[rn][kk + c + 4];
            }
#pragma unroll
            for (int mt = 0; mt < 2; mt++)
#pragma unroll
                for (int nt = 0; nt < 4; nt++)
                    mma_tf32(acc[mt][nt], af[mt], bf[nt]);
        }
        __syncthreads();
    }
#pragma unroll
    for (int mt = 0; mt < 2; mt++) {
        int row = bm + wm * 32 + mt * 16 + g;
#pragma unroll
        for (int nt = 0; nt < 4; nt++) {
            int col = h * HD + wn * 32 + nt * 8 + 2 * c;
            *(float2*)&o[(size_t)row * VS + col] =
                make_float2(acc[mt][nt][0], acc[mt][nt][1]);
            *(float2*)&o[(size_t)(row + 8) * VS + col] =
                make_float2(acc[mt][nt][2], acc[mt][nt][3]);
        }
    }
}

// ---------------- transpose: out[c][r] = in[r][c]; in [R x Cc] --------------
__global__ void transpose_k(const float* __restrict__ in, float* __restrict__ out,
                            int R, int Cc) {
    __shared__ float t[32][33];
    int c0 = blockIdx.x * 32, r0 = blockIdx.y * 32;
    int tx = threadIdx.x, ty = threadIdx.y;  // 32 x 8
#pragma unroll
    for (int i = 0; i < 4; i++)
        t[ty + i * 8][tx] = in[(size_t)(r0 + ty + i * 8) * Cc + c0 + tx];
    __syncthreads();
#pragma unroll
    for (int i = 0; i < 4; i++)
        out[(size_t)(c0 + ty + i * 8) * R + r0 + tx] = t[tx][ty + i * 8];
}

// ---------------- row softmax over 2048 cols --------------------------------
__global__ void softmax_row2048(const float* __restrict__ in, float* __restrict__ out,
                                float outscale) {
    __shared__ float sred[8];
    size_t row = blockIdx.x;
    const float* p = in + row * 2048;
    float* o = out + row * 2048;
    int tid = threadIdx.x;
    float v[8];
    float4 a = *(const float4*)&p[tid * 8];
    float4 b = *(const float4*)&p[tid * 8 + 4];
    v[0] = a.x; v[1] = a.y; v[2] = a.z; v[3] = a.w;
    v[4] = b.x; v[5] = b.y; v[6] = b.z; v[7] = b.w;
    float m = v[0];
#pragma unroll
    for (int i = 1; i < 8; i++) m = fmaxf(m, v[i]);
    m = blockRedMax(m, sred);
    float s = 0.0f;
#pragma unroll
    for (int i = 0; i < 8; i++) { v[i] = __expf(v[i] - m); s += v[i]; }
    s = blockRedSum(s, sred);
    float inv = outscale / s;
    float4 oa, ob;
    oa.x = v[0] * inv; oa.y = v[1] * inv; oa.z = v[2] * inv; oa.w = v[3] * inv;
    ob.x = v[4] * inv; ob.y = v[5] * inv; ob.z = v[6] * inv; ob.w = v[7] * inv;
    *(float4*)&o[tid * 8] = oa;
    *(float4*)&o[tid * 8 + 4] = ob;
}

// ---------------- fused residual + LayerNorm --------------------------------
__global__ void add_ln(const float* __restrict__ a, const float* __restrict__ b,
                       const float* __restrict__ g, const float* __restrict__ be,
                       float* __restrict__ out) {
    __shared__ float sred[8];
    int row = blockIdx.x;
    int tid = threadIdx.x;
    size_t base = (size_t)row * 1024 + tid * 4;
    float4 va = *(const float4*)&a[base];
    float4 vb = *(const float4*)&b[base];
    float4 s;
    s.x = va.x + vb.x; s.y = va.y + vb.y; s.z = va.z + vb.z; s.w = va.w + vb.w;
    float sum = s.x + s.y + s.z + s.w;
    float sq = s.x * s.x + s.y * s.y + s.z * s.z + s.w * s.w;
    sum = blockRedSum(sum, sred);
    sq = blockRedSum(sq, sred);
    float mean = sum * (1.0f / 1024.0f);
    float var = sq * (1.0f / 1024.0f) - mean * mean;
    float r = rsqrtf(var + 1e-5f);
    float4 vg = *(const float4*)&g[tid * 4];
    float4 vbe = *(const float4*)&be[tid * 4];
    float4 o;
    o.x = (s.x - mean) * r * vg.x + vbe.x;
    o.y = (s.y - mean) * r * vg.y + vbe.y;
    o.z = (s.z - mean) * r * vg.z + vbe.z;
    o.w = (s.w - mean) * r * vg.w + vbe.w;
    *(float4*)&out[base] = o;
}

// ---------------- launch ----------------------------------------------------
extern "C" void kernel_launch(void* const* d_in, const int* in_sizes, int n_in,
                              void* d_out, int out_size) {
    const float* x   = (const float*)d_in[0];
    const float* sp  = (const float*)d_in[1];
    const float* Wq  = (const float*)d_in[2];
    const float* bq  = (const float*)d_in[3];
    const float* Wk  = (const float*)d_in[4];
    const float* bk  = (const float*)d_in[5];
    const float* Wv  = (const float*)d_in[6];
    const float* bv  = (const float*)d_in[7];
    const float* Wqp = (const float*)d_in[8];
    const float* bqp = (const float*)d_in[9];
    const float* Wkp = (const float*)d_in[10];
    const float* bkp = (const float*)d_in[11];
    const float* Wvp = (const float*)d_in[12];
    const float* bvp = (const float*)d_in[13];
    const float* Wo  = (const float*)d_in[14];
    const float* bo  = (const float*)d_in[15];
    const float* W1  = (const float*)d_in[16];
    const float* b1  = (const float*)d_in[17];
    const float* W2  = (const float*)d_in[18];
    const float* b2  = (const float*)d_in[19];
    const float* g1  = (const float*)d_in[20];
    const float* be1 = (const float*)d_in[21];
    const float* g2  = (const float*)d_in[22];
    const float* be2 = (const float*)d_in[23];
    float* out = (float*)d_out;

    float *pq, *pk, *pv, *pvt, *pt0, *patt, *psp, *po, *ph, *pf;
    cudaGetSymbolAddress((void**)&pq,  g_q);
    cudaGetSymbolAddress((void**)&pk,  g_k);
    cudaGetSymbolAddress((void**)&pv,  g_v);
    cudaGetSymbolAddress((void**)&pvt, g_vt);
    cudaGetSymbolAddress((void**)&pt0, g_t0);
    cudaGetSymbolAddress((void**)&patt, g_att);
    cudaGetSymbolAddress((void**)&psp, g_sp);
    cudaGetSymbolAddress((void**)&po,  g_o);
    cudaGetSymbolAddress((void**)&ph,  g_h);
    cudaGetSymbolAddress((void**)&pf,  g_f);

    dim3 blk(256);

    // Q/K/V double projections (tensor cores, cp.async pipelined)
    gemm_tc<0><<<dim3(KS / 128, L / 128), blk>>>(x,   Wq,  bq,  pt0, L, KS, D);
    gemm_tc<0><<<dim3(KS / 128, L / 128), blk>>>(pt0, Wqp, bqp, pq,  L, KS, KS);
    gemm_tc<0><<<dim3(KS / 128, L / 128), blk>>>(x,   Wk,  bk,  pt0, L, KS, D);
    gemm_tc<0><<<dim3(KS / 128, L / 128), blk>>>(pt0, Wkp, bkp, pk,  L, KS, KS);
    gemm_tc<0><<<dim3(VS / 128, L / 128), blk>>>(x,   Wv,  bv,  pt0, L, VS, D);
    gemm_tc<0><<<dim3(VS / 128, L / 128), blk>>>(pt0, Wvp, bvp, pv,  L, VS, VS);

    // v transpose for AV mma
    transpose_k<<<dim3(VS / 32, L / 32), dim3(32, 8)>>>(pv, pvt, L, VS);

    // sp_bias = 0.5 * softmax(shortest_path, axis=-1)
    softmax_row2048<<<L, blk>>>(sp, psp, 0.5f);

    // att = softmax(qk^T/8 + sp_bias)
    attn_scores_tc<<<dim3(L / 128, L / 128, H), blk>>>(pq, pk, psp, patt);
    softmax_row2048<<<H * L, blk>>>(patt, patt, 1.0f);

    // context = att @ v
    attn_av_tc<<<dim3(1, L / 128, H), blk>>>(patt, pvt, po);

    // o-proj, residual + LN1
    gemm_tc<0><<<dim3(D / 128, L / 128), blk>>>(po, Wo, bo, pf, L, D, VS);
    add_ln<<<L, blk>>>(x, pf, g1, be1, ph);

    // FFN, residual + LN2
    gemm_tc<1><<<dim3(HID / 128, L / 128), blk>>>(ph,  W1, b1, pt0, L, HID, D);
    gemm_tc<1><<<dim3(D / 128, L / 128), blk>>>(pt0, W2, b2, pf,  L, D, HID);
    add_ln<<<L, blk>>>(ph, pf, g2, be2, out);
}

// round 7
// speedup vs baseline: 3.1818x; 1.0735x over previous
#include <cuda_runtime.h>
#include <cstddef>
#include <cstdint>

#define L   2048
#define D   1024
#define H   16
#define KS  1024
#define VS  1024
#define HID 4096
#define HD  64

// ---------------- scratch (device globals; no allocation allowed) ----------
__device__ float g_q[L * KS];                 // 8 MB
__device__ float g_k[L * KS];                 // 8 MB
__device__ float g_v[L * VS];                 // 8 MB
__device__ float g_vt[VS * L];                // 8 MB (V transposed)
__device__ float g_t0[L * HID];               // 32 MB (qkv stage-1 slices / FFN hidden)
__device__ float g_att[(size_t)H * L * L];    // 256 MB
__device__ float g_sp[L * L];                 // 16 MB
__device__ float g_o[L * VS];                 // 8 MB
__device__ float g_h[L * D];                  // 8 MB
__device__ float g_f[L * D];                  // 8 MB

// ---------------- helpers ---------------------------------------------------
__device__ __forceinline__ unsigned f2tf32(float x) {
    unsigned r;
    asm("cvt.rna.tf32.f32 %0, %1;" : "=r"(r) : "f"(x));
    return r;
}

__device__ __forceinline__ void mma_tf32(float* c, const unsigned* a, const unsigned* b) {
    asm volatile(
        "mma.sync.aligned.m16n8k8.row.col.f32.tf32.tf32.f32 "
        "{%0,%1,%2,%3}, {%4,%5,%6,%7}, {%8,%9}, {%0,%1,%2,%3};\n"
        : "+f"(c[0]), "+f"(c[1]), "+f"(c[2]), "+f"(c[3])
        : "r"(a[0]), "r"(a[1]), "r"(a[2]), "r"(a[3]), "r"(b[0]), "r"(b[1]));
}

__device__ __forceinline__ void cp16(unsigned dst, const void* src) {
    asm volatile("cp.async.ca.shared.global [%0], [%1], 16;\n" :: "r"(dst), "l"(src));
}
#define CP_COMMIT() asm volatile("cp.async.commit_group;\n" ::: "memory")
#define CP_WAIT1()  asm volatile("cp.async.wait_group 1;\n" ::: "memory")
#define CP_WAIT0()  asm volatile("cp.async.wait_group 0;\n" ::: "memory")

__device__ __forceinline__ float warpRedSum(float v) {
#pragma unroll
    for (int o = 16; o > 0; o >>= 1) v += __shfl_xor_sync(0xffffffffu, v, o);
    return v;
}
__device__ __forceinline__ float warpRedMax(float v) {
#pragma unroll
    for (int o = 16; o > 0; o >>= 1) v = fmaxf(v, __shfl_xor_sync(0xffffffffu, v, o));
    return v;
}
__device__ __forceinline__ float blockRedSum(float v, float* sred) {
    int lane = threadIdx.x & 31, w = threadIdx.x >> 5;
    v = warpRedSum(v);
    if (lane == 0) sred[w] = v;
    __syncthreads();
    float r;
    if (threadIdx.x < 32) {
        r = (threadIdx.x < 8) ? sred[threadIdx.x] : 0.0f;
        r = warpRedSum(r);
        if (threadIdx.x == 0) sred[0] = r;
    }
    __syncthreads();
    r = sred[0];
    __syncthreads();
    return r;
}
__device__ __forceinline__ float blockRedMax(float v, float* sred) {
    int lane = threadIdx.x & 31, w = threadIdx.x >> 5;
    v = warpRedMax(v);
    if (lane == 0) sred[w] = v;
    __syncthreads();
    float r;
    if (threadIdx.x < 32) {
        r = (threadIdx.x < 8) ? sred[threadIdx.x] : -3.4e38f;
        r = warpRedMax(r);
        if (threadIdx.x == 0) sred[0] = r;
    }
    __syncthreads();
    r = sred[0];
    __syncthreads();
    return r;
}

// ---------------- TF32 NT GEMM body: 128x128 tile, BK=16, 512 threads -------
// Warps 4(m) x 4(n); warp tile 32x32: 2 m16-tiles x 4 n8-tiles.
// cp.async double-buffered; fp32 in smem, tf32 cvt at fragment load.
template <int RELU>
__device__ __forceinline__ void gemm_body(const float* __restrict__ A,
                                          const float* __restrict__ W,
                                          const float* __restrict__ bias,
                                          float* __restrict__ C, int N, int K) {
    __shared__ float As[2][128][20];
    __shared__ float Ws[2][128][20];
    int tid = threadIdx.x;
    int wid = tid >> 5, lane = tid & 31;
    int g = lane >> 2, c = lane & 3;
    int wm = wid >> 2, wn = wid & 3;
    int bm = blockIdx.y * 128, bn = blockIdx.x * 128;

    float acc[2][4][4] = {};

    int lrow = tid >> 2;            // 0..127
    int lcol = (tid & 3) << 2;      // 0,4,8,12
    const float* Ap = A + (size_t)(bm + lrow) * K + lcol;
    const float* Wp = W + (size_t)(bn + lrow) * K + lcol;

    unsigned da0 = (unsigned)__cvta_generic_to_shared(&As[0][lrow][lcol]);
    unsigned dw0 = (unsigned)__cvta_generic_to_shared(&Ws[0][lrow][lcol]);
    const unsigned stage_off = 128 * 20 * 4;

    cp16(da0, Ap);
    cp16(dw0, Wp);
    CP_COMMIT();

    for (int k0 = 0; k0 < K; k0 += 16) {
        int s = (k0 >> 4) & 1;
        if (k0 + 16 < K) {
            cp16(da0 + (s ^ 1) * stage_off, Ap + k0 + 16);
            cp16(dw0 + (s ^ 1) * stage_off, Wp + k0 + 16);
            CP_COMMIT();
            CP_WAIT1();
        } else {
            CP_WAIT0();
        }
        __syncthreads();
#pragma unroll
        for (int ks = 0; ks < 2; ks++) {
            int kk = ks * 8;
            unsigned af[2][4], bf[4][2];
#pragma unroll
            for (int mt = 0; mt < 2; mt++) {
                int rm = wm * 32 + mt * 16 + g;
                af[mt][0] = f2tf32(As[s][rm][kk + c]);
                af[mt][1] = f2tf32(As[s][rm + 8][kk + c]);
                af[mt][2] = f2tf32(As[s][rm][kk + c + 4]);
                af[mt][3] = f2tf32(As[s][rm + 8][kk + c + 4]);
            }
#pragma unroll
            for (int nt = 0; nt < 4; nt++) {
                int rn = wn * 32 + nt * 8 + g;
                bf[nt][0] = f2tf32(Ws[s][rn][kk + c]);
                bf[nt][1] = f2tf32(Ws[s][rn][kk + c + 4]);
            }
#pragma unroll
            for (int mt = 0; mt < 2; mt++)
#pragma unroll
                for (int nt = 0; nt < 4; nt++)
                    mma_tf32(acc[mt][nt], af[mt], bf[nt]);
        }
        __syncthreads();
    }
#pragma unroll
    for (int mt = 0; mt < 2; mt++) {
        int row = bm + wm * 32 + mt * 16 + g;
#pragma unroll
        for (int nt = 0; nt < 4; nt++) {
            int col = bn + wn * 32 + nt * 8 + 2 * c;
            float2 bv = *(const float2*)&bias[col];
            float v0 = acc[mt][nt][0] + bv.x;
            float v1 = acc[mt][nt][1] + bv.y;
            float v2 = acc[mt][nt][2] + bv.x;
            float v3 = acc[mt][nt][3] + bv.y;
            if (RELU) {
                v0 = fmaxf(v0, 0.0f); v1 = fmaxf(v1, 0.0f);
                v2 = fmaxf(v2, 0.0f); v3 = fmaxf(v3, 0.0f);
            }
            *(float2*)&C[(size_t)row * N + col] = make_float2(v0, v1);
            *(float2*)&C[(size_t)(row + 8) * N + col] = make_float2(v2, v3);
        }
    }
}

template <int RELU>
__global__ void __launch_bounds__(512)
gemm_tc(const float* __restrict__ A, const float* __restrict__ W,
        const float* __restrict__ bias, float* __restrict__ C, int N, int K) {
    gemm_body<RELU>(A, W, bias, C, N, K);
}

// Merged 3-way GEMM: blockIdx.z selects (A, W, bias, C). Stage-1 passes same A.
__global__ void __launch_bounds__(512)
gemm_tc3(const float* __restrict__ A0, const float* __restrict__ A1,
         const float* __restrict__ A2,
         const float* __restrict__ W0, const float* __restrict__ W1,
         const float* __restrict__ W2,
         const float* __restrict__ b0, const float* __restrict__ b1,
         const float* __restrict__ b2,
         float* __restrict__ C0, float* __restrict__ C1, float* __restrict__ C2,
         int N, int K) {
    int z = blockIdx.z;
    const float* A = (z == 0) ? A0 : (z == 1) ? A1 : A2;
    const float* W = (z == 0) ? W0 : (z == 1) ? W1 : W2;
    const float* b = (z == 0) ? b0 : (z == 1) ? b1 : b2;
    float* C = (z == 0) ? C0 : (z == 1) ? C1 : C2;
    gemm_body<0>(A, W, b, C, N, K);
}

// ---------------- attention scores (TF32 MMA) -------------------------------
// att[h] = q_h @ k_h^T * 0.125 + sp. 256 threads, warps 2x4, K=64 (short).
__global__ void attn_scores_tc(const float* __restrict__ q, const float* __restrict__ k,
                               const float* __restrict__ sp, float* __restrict__ att) {
    __shared__ unsigned As[128][20];
    __shared__ unsigned Ws[128][20];
    int h = blockIdx.z;
    int tid = threadIdx.x;
    int wid = tid >> 5, lane = tid & 31;
    int g = lane >> 2, c = lane & 3;
    int wm = wid >> 2, wn = wid & 3;
    int bm = blockIdx.y * 128, bn = blockIdx.x * 128;

    float acc[4][4][4] = {};

    int lr = tid >> 1, lkc = (tid & 1) * 8;
    const float* Ap = q + h * HD + (size_t)(bm + lr) * KS + lkc;
    const float* Wp = k + h * HD + (size_t)(bn + lr) * KS + lkc;

    for (int k0 = 0; k0 < HD; k0 += 16) {
        float4 a0 = *(const float4*)(Ap + k0);
        float4 a1 = *(const float4*)(Ap + k0 + 4);
        float4 w0 = *(const float4*)(Wp + k0);
        float4 w1 = *(const float4*)(Wp + k0 + 4);
        uint4 ua0 = {f2tf32(a0.x), f2tf32(a0.y), f2tf32(a0.z), f2tf32(a0.w)};
        uint4 ua1 = {f2tf32(a1.x), f2tf32(a1.y), f2tf32(a1.z), f2tf32(a1.w)};
        uint4 uw0 = {f2tf32(w0.x), f2tf32(w0.y), f2tf32(w0.z), f2tf32(w0.w)};
        uint4 uw1 = {f2tf32(w1.x), f2tf32(w1.y), f2tf32(w1.z), f2tf32(w1.w)};
        *(uint4*)&As[lr][lkc]     = ua0;
        *(uint4*)&As[lr][lkc + 4] = ua1;
        *(uint4*)&Ws[lr][lkc]     = uw0;
        *(uint4*)&Ws[lr][lkc + 4] = uw1;
        __syncthreads();
#pragma unroll
        for (int ks = 0; ks < 2; ks++) {
            int kk = ks * 8;
            unsigned af[4][4], bf[4][2];
#pragma unroll
            for (int mt = 0; mt < 4; mt++) {
                int rm = wm * 64 + mt * 16 + g;
                af[mt][0] = As[rm][kk + c];
                af[mt][1] = As[rm + 8][kk + c];
                af[mt][2] = As[rm][kk + c + 4];
                af[mt][3] = As[rm + 8][kk + c + 4];
            }
#pragma unroll
            for (int nt = 0; nt < 4; nt++) {
                int rn = wn * 32 + nt * 8 + g;
                bf[nt][0] = Ws[rn][kk + c];
                bf[nt][1] = Ws[rn][kk + c + 4];
            }
#pragma unroll
            for (int mt = 0; mt < 4; mt++)
#pragma unroll
                for (int nt = 0; nt < 4; nt++)
                    mma_tf32(acc[mt][nt], af[mt], bf[nt]);
        }
        __syncthreads();
    }
    size_t base = (size_t)h * L * L;
#pragma unroll
    for (int mt = 0; mt < 4; mt++) {
        int row = bm + wm * 64 + mt * 16 + g;
#pragma unroll
        for (int nt = 0; nt < 4; nt++) {
            int col = bn + wn * 32 + nt * 8 + 2 * c;
            float2 s0 = *(const float2*)&sp[(size_t)row * L + col];
            float2 s1 = *(const float2*)&sp[(size_t)(row + 8) * L + col];
            *(float2*)&att[base + (size_t)row * L + col] =
                make_float2(acc[mt][nt][0] * 0.125f + s0.x, acc[mt][nt][1] * 0.125f + s0.y);
            *(float2*)&att[base + (size_t)(row + 8) * L + col] =
                make_float2(acc[mt][nt][2] * 0.125f + s1.x, acc[mt][nt][3] * 0.125f + s1.y);
        }
    }
}

// ---------------- AV (TF32 MMA, cp.async pipelined) -------------------------
// o[:, h*64:+64] = att[h] @ vt_h^T. vt: [VS, L]. 128x64 tile, 256 threads.
// Warps 4(m) x 2(n); warp tile 32x32.
__global__ void __launch_bounds__(256)
attn_av_tc(const float* __restrict__ att, const float* __restrict__ vt,
           float* __restrict__ o) {
    __shared__ float As[2][128][20];
    __shared__ float Ws[2][64][20];
    int h = blockIdx.z;
    int tid = threadIdx.x;
    int wid = tid >> 5, lane = tid & 31;
    int g = lane >> 2, c = lane & 3;
    int wm = wid >> 1, wn = wid & 1;
    int bm = blockIdx.y * 128;

    float acc[2][4][4] = {};

    int lr = tid >> 1, lcol = (tid & 1) * 8;
    const float* Ap = att + (size_t)h * L * L + (size_t)(bm + lr) * L + lcol;
    int wr = tid >> 2, wkc = (tid & 3) * 4;
    const float* Wp = vt + (size_t)(h * HD + wr) * L + wkc;

    unsigned da0 = (unsigned)__cvta_generic_to_shared(&As[0][lr][lcol]);
    unsigned dw0 = (unsigned)__cvta_generic_to_shared(&Ws[0][wr][wkc]);
    const unsigned a_off = 128 * 20 * 4;
    const unsigned w_off = 64 * 20 * 4;

    cp16(da0, Ap);    cp16(da0 + 16, Ap + 4);
    cp16(dw0, Wp);
    CP_COMMIT();

    for (int k0 = 0; k0 < L; k0 += 16) {
        int s = (k0 >> 4) & 1;
        if (k0 + 16 < L) {
            cp16(da0 + (s ^ 1) * a_off, Ap + k0 + 16);
            cp16(da0 + (s ^ 1) * a_off + 16, Ap + k0 + 20);
            cp16(dw0 + (s ^ 1) * w_off, Wp + k0 + 16);
            CP_COMMIT();
            CP_WAIT1();
        } else {
            CP_WAIT0();
        }
        __syncthreads();
#pragma unroll
        for (int ks = 0; ks < 2; ks++) {
            int kk = ks * 8;
            unsigned af[2][4], bf[4][2];
#pragma unroll
            for (int mt = 0; mt < 2; mt++) {
                int rm = wm * 32 + mt * 16 + g;
                af[mt][0] = f2tf32(As[s][rm][kk + c]);
                af[mt][1] = f2tf32(As[s][rm + 8][kk + c]);
                af[mt][2] = f2tf32(As[s][rm][kk + c + 4]);
                af[mt][3] = f2tf32(As[s][rm + 8][kk + c + 4]);
            }
#pragma unroll
            for (int nt = 0; nt < 4; nt++) {
                int rn = wn * 32 + nt * 8 + g;
                bf[nt][0] = f2tf32(Ws[s][rn][kk + c]);
                bf[nt][1] = f2tf32(Ws[s][rn][kk + c + 4]);
            }
#pragma unroll
            for (int mt = 0; mt < 2; mt++)
#pragma unroll
                for (int nt = 0; nt < 4; nt++)
                    mma_tf32(acc[mt][nt], af[mt], bf[nt]);
        }
        __syncthreads();
    }
#pragma unroll
    for (int mt = 0; mt < 2; mt++) {
        int row = bm + wm * 32 + mt * 16 + g;
#pragma unroll
        for (int nt = 0; nt < 4; nt++) {
            int col = h * HD + wn * 32 + nt * 8 + 2 * c;
            *(float2*)&o[(size_t)row * VS + col] =
                make_float2(acc[mt][nt][0], acc[mt][nt][1]);
            *(float2*)&o[(size_t)(row + 8) * VS + col] =
                make_float2(acc[mt][nt][2], acc[mt][nt][3]);
        }
    }
}

// ---------------- transpose: out[c][r] = in[r][c]; in [R x Cc] --------------
__global__ void transpose_k(const float* __restrict__ in, float* __restrict__ out,
                            int R, int Cc) {
    __shared__ float t[32][33];
    int c0 = blockIdx.x * 32, r0 = blockIdx.y * 32;
    int tx = threadIdx.x, ty = threadIdx.y;  // 32 x 8
#pragma unroll
    for (int i = 0; i < 4; i++)
        t[ty + i * 8][tx] = in[(size_t)(r0 + ty + i * 8) * Cc + c0 + tx];
    __syncthreads();
#pragma unroll
    for (int i = 0; i < 4; i++)
        out[(size_t)(c0 + ty + i * 8) * R + r0 + tx] = t[tx][ty + i * 8];
}

// ---------------- row softmax over 2048 cols --------------------------------
__global__ void softmax_row2048(const float* __restrict__ in, float* __restrict__ out,
                                float outscale) {
    __shared__ float sred[8];
    size_t row = blockIdx.x;
    const float* p = in + row * 2048;
    float* o = out + row * 2048;
    int tid = threadIdx.x;
    float v[8];
    float4 a = *(const float4*)&p[tid * 8];
    float4 b = *(const float4*)&p[tid * 8 + 4];
    v[0] = a.x; v[1] = a.y; v[2] = a.z; v[3] = a.w;
    v[4] = b.x; v[5] = b.y; v[6] = b.z; v[7] = b.w;
    float m = v[0];
#pragma unroll
    for (int i = 1; i < 8; i++) m = fmaxf(m, v[i]);
    m = blockRedMax(m, sred);
    float s = 0.0f;
#pragma unroll
    for (int i = 0; i < 8; i++) { v[i] = __expf(v[i] - m); s += v[i]; }
    s = blockRedSum(s, sred);
    float inv = outscale / s;
    float4 oa, ob;
    oa.x = v[0] * inv; oa.y = v[1] * inv; oa.z = v[2] * inv; oa.w = v[3] * inv;
    ob.x = v[4] * inv; ob.y = v[5] * inv; ob.z = v[6] * inv; ob.w = v[7] * inv;
    *(float4*)&o[tid * 8] = oa;
    *(float4*)&o[tid * 8 + 4] = ob;
}

// ---------------- fused residual + LayerNorm --------------------------------
__global__ void add_ln(const float* __restrict__ a, const float* __restrict__ b,
                       const float* __restrict__ g, const float* __restrict__ be,
                       float* __restrict__ out) {
    __shared__ float sred[8];
    int row = blockIdx.x;
    int tid = threadIdx.x;
    size_t base = (size_t)row * 1024 + tid * 4;
    float4 va = *(const float4*)&a[base];
    float4 vb = *(const float4*)&b[base];
    float4 s;
    s.x = va.x + vb.x; s.y = va.y + vb.y; s.z = va.z + vb.z; s.w = va.w + vb.w;
    float sum = s.x + s.y + s.z + s.w;
    float sq = s.x * s.x + s.y * s.y + s.z * s.z + s.w * s.w;
    sum = blockRedSum(sum, sred);
    sq = blockRedSum(sq, sred);
    float mean = sum * (1.0f / 1024.0f);
    float var = sq * (1.0f / 1024.0f) - mean * mean;
    float r = rsqrtf(var + 1e-5f);
    float4 vg = *(const float4*)&g[tid * 4];
    float4 vbe = *(const float4*)&be[tid * 4];
    float4 o;
    o.x = (s.x - mean) * r * vg.x + vbe.x;
    o.y = (s.y - mean) * r * vg.y + vbe.y;
    o.z = (s.z - mean) * r * vg.z + vbe.z;
    o.w = (s.w - mean) * r * vg.w + vbe.w;
    *(float4*)&out[base] = o;
}

// ---------------- launch ----------------------------------------------------
extern "C" void kernel_launch(void* const* d_in, const int* in_sizes, int n_in,
                              void* d_out, int out_size) {
    const float* x   = (const float*)d_in[0];
    const float* sp  = (const float*)d_in[1];
    const float* Wq  = (const float*)d_in[2];
    const float* bq  = (const float*)d_in[3];
    const float* Wk  = (const float*)d_in[4];
    const float* bk  = (const float*)d_in[5];
    const float* Wv  = (const float*)d_in[6];
    const float* bv  = (const float*)d_in[7];
    const float* Wqp = (const float*)d_in[8];
    const float* bqp = (const float*)d_in[9];
    const float* Wkp = (const float*)d_in[10];
    const float* bkp = (const float*)d_in[11];
    const float* Wvp = (const float*)d_in[12];
    const float* bvp = (const float*)d_in[13];
    const float* Wo  = (const float*)d_in[14];
    const float* bo  = (const float*)d_in[15];
    const float* W1  = (const float*)d_in[16];
    const float* b1  = (const float*)d_in[17];
    const float* W2  = (const float*)d_in[18];
    const float* b2  = (const float*)d_in[19];
    const float* g1  = (const float*)d_in[20];
    const float* be1 = (const float*)d_in[21];
    const float* g2  = (const float*)d_in[22];
    const float* be2 = (const float*)d_in[23];
    float* out = (float*)d_out;

    float *pq, *pk, *pv, *pvt, *pt0, *patt, *psp, *po, *ph, *pf;
    cudaGetSymbolAddress((void**)&pq,  g_q);
    cudaGetSymbolAddress((void**)&pk,  g_k);
    cudaGetSymbolAddress((void**)&pv,  g_v);
    cudaGetSymbolAddress((void**)&pvt, g_vt);
    cudaGetSymbolAddress((void**)&pt0, g_t0);
    cudaGetSymbolAddress((void**)&patt, g_att);
    cudaGetSymbolAddress((void**)&psp, g_sp);
    cudaGetSymbolAddress((void**)&po,  g_o);
    cudaGetSymbolAddress((void**)&ph,  g_h);
    cudaGetSymbolAddress((void**)&pf,  g_f);

    float* t0a = pt0;
    float* t0b = pt0 + (size_t)L * KS;
    float* t0c = pt0 + (size_t)2 * L * KS;

    dim3 blk256(256), blk512(512);

    // QKV stage-1 (shared A = x), merged into one launch
    gemm_tc3<<<dim3(KS / 128, L / 128, 3), blk512>>>(
        x, x, x, Wq, Wk, Wv, bq, bk, bv, t0a, t0b, t0c, KS, D);
    // QKV stage-2, merged
    gemm_tc3<<<dim3(KS / 128, L / 128, 3), blk512>>>(
        t0a, t0b, t0c, Wqp, Wkp, Wvp, bqp, bkp, bvp, pq, pk, pv, KS, KS);

    // v transpose for AV mma
    transpose_k<<<dim3(VS / 32, L / 32), dim3(32, 8)>>>(pv, pvt, L, VS);

    // sp_bias = 0.5 * softmax(shortest_path, axis=-1)
    softmax_row2048<<<L, blk256>>>(sp, psp, 0.5f);

    // att = softmax(qk^T/8 + sp_bias)
    attn_scores_tc<<<dim3(L / 128, L / 128, H), blk256>>>(pq, pk, psp, patt);
    softmax_row2048<<<H * L, blk256>>>(patt, patt, 1.0f);

    // context = att @ v
    attn_av_tc<<<dim3(1, L / 128, H), blk256>>>(patt, pvt, po);

    // o-proj, residual + LN1
    gemm_tc<0><<<dim3(D / 128, L / 128), blk512>>>(po, Wo, bo, pf, D, VS);
    add_ln<<<L, blk256>>>(x, pf, g1, be1, ph);

    // FFN, residual + LN2
    gemm_tc<1><<<dim3(HID / 128, L / 128), blk512>>>(ph, W1, b1, pt0, HID, D);
    gemm_tc<1><<<dim3(D / 128, L / 128), blk512>>>(pt0, W2, b2, pf, D, HID);
    add_ln<<<L, blk256>>>(ph, pf, g2, be2, out);
}